// round 3
// baseline (speedup 1.0000x reference)
#include <cuda_runtime.h>
#include <cuda_bf16.h>

// img : (1, 64, 64, 1024) float32, NHWC
// rois: (1, 512, 4) int32  -> (x, y, w, h)
// out : (1, 512, 7, 7, 1024) float32
#define POOL    7
#define NROIS   512
#define IMG_W   64
#define NCELLS  (NROIS * POOL * POOL)   // 25088
#define NUNITS  (NCELLS * 2)            // 50176 half-cells (128 float4 lanes each)
#define GRID    1184                    // 148 SMs * 8 CTAs

struct Unit {
    unsigned o00, o01, o10, o11;   // img offsets in float4 units
    unsigned oout;                 // out offset in float4 units
    float w00, w01, w10, w11;
};

__device__ __forceinline__ Unit make_unit(int unit, const int* __restrict__ rois, int lane)
{
    const int cell = unit >> 1;
    const int half = unit & 1;
    const int roi  = cell / (POOL * POOL);
    const int rem  = cell - roi * (POOL * POOL);
    const int py   = rem / POOL;
    const int px   = rem - py * POOL;

    const int4 r = __ldg(((const int4*)rois) + roi);   // x,y,w,h

    // Match reference arithmetic exactly: s = i * (dim / 7.0f) in fp32
    const float sy = (float)py * ((float)r.w / (float)POOL);
    const float sx = (float)px * ((float)r.z / (float)POOL);
    const int   y0 = (int)sy;
    const int   x0 = (int)sx;
    const float fy = sy - (float)y0;
    const float fx = sx - (float)x0;
    const int   y1 = min(y0 + 1, r.w - 1);
    const int   x1 = min(x0 + 1, r.z - 1);

    Unit u;
    u.w11 = fx * fy;
    u.w01 = fx - u.w11;          // fx*(1-fy)
    u.w10 = fy - u.w11;          // (1-fx)*fy
    u.w00 = 1.0f - fx - u.w10;   // (1-fx)*(1-fy)

    const int gy0 = r.y + y0, gy1 = r.y + y1;
    const int gx0 = r.x + x0, gx1 = r.x + x1;
    const int c   = (half << 7) + lane;                // 0..255 float4 lane

    u.o00 = (unsigned)(gy0 * IMG_W + gx0) * 256u + c;
    u.o01 = (unsigned)(gy0 * IMG_W + gx1) * 256u + c;
    u.o10 = (unsigned)(gy1 * IMG_W + gx0) * 256u + c;
    u.o11 = (unsigned)(gy1 * IMG_W + gx1) * 256u + c;
    u.oout = (unsigned)cell * 256u + c;
    return u;
}

__device__ __forceinline__ float4 blend(const float4 v00, const float4 v01,
                                        const float4 v10, const float4 v11,
                                        float w00, float w01, float w10, float w11)
{
    float4 o;
    o.x = fmaf(v11.x, w11, fmaf(v10.x, w10, fmaf(v01.x, w01, v00.x * w00)));
    o.y = fmaf(v11.y, w11, fmaf(v10.y, w10, fmaf(v01.y, w01, v00.y * w00)));
    o.z = fmaf(v11.z, w11, fmaf(v10.z, w10, fmaf(v01.z, w01, v00.z * w00)));
    o.w = fmaf(v11.w, w11, fmaf(v10.w, w10, fmaf(v01.w, w01, v00.w * w00)));
    return o;
}

// Persistent grid-stride kernel with 1-deep software pipeline: loads for unit
// i+1 are issued before unit i's compute+store, so each thread keeps up to 8
// independent 16B loads in flight across the whole run.
__global__ __launch_bounds__(128, 8)
void roi_pool_kernel(const float* __restrict__ img,
                     const int*   __restrict__ rois,
                     float*       __restrict__ out)
{
    const float4* ibase = (const float4*)img;
    float4*       obase = (float4*)out;
    const int lane   = threadIdx.x;
    const int stride = gridDim.x;

    int u = blockIdx.x;
    if (u >= NUNITS) return;

    Unit cur = make_unit(u, rois, lane);
    float4 a00 = __ldg(ibase + cur.o00);
    float4 a01 = __ldg(ibase + cur.o01);
    float4 a10 = __ldg(ibase + cur.o10);
    float4 a11 = __ldg(ibase + cur.o11);

    for (u += stride; u < NUNITS; u += stride) {
        Unit nxt = make_unit(u, rois, lane);
        // Prefetch next unit's data before consuming current regs.
        float4 b00 = __ldg(ibase + nxt.o00);
        float4 b01 = __ldg(ibase + nxt.o01);
        float4 b10 = __ldg(ibase + nxt.o10);
        float4 b11 = __ldg(ibase + nxt.o11);

        obase[cur.oout] = blend(a00, a01, a10, a11,
                                cur.w00, cur.w01, cur.w10, cur.w11);

        cur = nxt;
        a00 = b00; a01 = b01; a10 = b10; a11 = b11;
    }

    obase[cur.oout] = blend(a00, a01, a10, a11,
                            cur.w00, cur.w01, cur.w10, cur.w11);
}

extern "C" void kernel_launch(void* const* d_in, const int* in_sizes, int n_in,
                              void* d_out, int out_size)
{
    const float* img  = (const float*)d_in[0];
    const int*   rois = (const int*)d_in[1];
    float*       out  = (float*)d_out;

    roi_pool_kernel<<<GRID, 128>>>(img, rois, out);
}

// round 4
// speedup vs baseline: 1.2019x; 1.2019x over previous
#include <cuda_runtime.h>
#include <cuda_bf16.h>

// img : (1, 64, 64, 1024) float32, NHWC
// rois: (1, 512, 4) int32  -> (x, y, w, h)
// out : (1, 512, 7, 7, 1024) float32
#define POOL   7
#define NROIS  512
#define IMG_W  64

// One CTA per (roi, py) output row: 7 cells, 256 threads, 1 float4 lane each.
// ROI params / fy / row bases are loop-invariant; the px loop is software-
// pipelined depth-1 so each thread keeps up to 8 independent 16B loads in
// flight while blending the previous cell.
__global__ __launch_bounds__(256)
void roi_pool_kernel(const float* __restrict__ img,
                     const int*   __restrict__ rois,
                     float*       __restrict__ out)
{
    const int bid = blockIdx.x;           // roi*7 + py
    const int roi = bid / POOL;
    const int py  = bid - roi * POOL;

    const int4 r = __ldg(((const int4*)rois) + roi);   // x, y, w, h

    // Loop-invariant y-axis work (match reference fp32 arithmetic exactly)
    const float stepy = (float)r.w / (float)POOL;
    const float stepx = (float)r.z / (float)POOL;
    const float sy = (float)py * stepy;
    const int   y0 = (int)sy;
    const float fy = sy - (float)y0;
    const int   y1 = min(y0 + 1, r.w - 1);

    const int c = threadIdx.x;            // 0..255 float4 lane
    const float4* ibase = (const float4*)img;
    // Row bases in float4 units, already including roi x-origin and lane.
    const unsigned row0 = (unsigned)((r.y + y0) * IMG_W + r.x) * 256u + c;
    const unsigned row1 = (unsigned)((r.y + y1) * IMG_W + r.x) * 256u + c;
    const int wm1 = r.z - 1;

    // Output: cells (roi*49 + py*7 + px) are consecutive -> +256 per px.
    float4* optr = (float4*)out + ((size_t)(roi * POOL + py) * POOL) * 256 + c;

    // ---- prologue: px = 0 (sx = 0, x0 = 0, fx = 0, x1 = min(1, w-1)) ----
    float fxc = 0.0f;
    {
        const int x1 = min(1, wm1);
        // cur loads
        float4 a00 = __ldg(ibase + row0);
        float4 a01 = __ldg(ibase + row0 + (unsigned)x1 * 256u);
        float4 a10 = __ldg(ibase + row1);
        float4 a11 = __ldg(ibase + row1 + (unsigned)x1 * 256u);

        #pragma unroll
        for (int px = 1; px < POOL; ++px) {
            // next cell index math (cheap, loop-invariant bases)
            const float sx = (float)px * stepx;
            const int   x0 = (int)sx;
            const float fxn = sx - (float)x0;
            const int   x1n = min(x0 + 1, wm1);

            // prefetch next cell's four pixels
            const float4 b00 = __ldg(ibase + row0 + (unsigned)x0  * 256u);
            const float4 b01 = __ldg(ibase + row0 + (unsigned)x1n * 256u);
            const float4 b10 = __ldg(ibase + row1 + (unsigned)x0  * 256u);
            const float4 b11 = __ldg(ibase + row1 + (unsigned)x1n * 256u);

            // blend + store current cell (weights from fxc, fy)
            const float w11 = fxc * fy;
            const float w01 = fxc - w11;
            const float w10 = fy - w11;
            const float w00 = 1.0f - fxc - w10;
            float4 o;
            o.x = fmaf(a11.x, w11, fmaf(a10.x, w10, fmaf(a01.x, w01, a00.x * w00)));
            o.y = fmaf(a11.y, w11, fmaf(a10.y, w10, fmaf(a01.y, w01, a00.y * w00)));
            o.z = fmaf(a11.z, w11, fmaf(a10.z, w10, fmaf(a01.z, w01, a00.z * w00)));
            o.w = fmaf(a11.w, w11, fmaf(a10.w, w10, fmaf(a01.w, w01, a00.w * w00)));
            *optr = o;
            optr += 256;

            a00 = b00; a01 = b01; a10 = b10; a11 = b11;
            fxc = fxn;
        }

        // ---- epilogue: px = 6 ----
        const float w11 = fxc * fy;
        const float w01 = fxc - w11;
        const float w10 = fy - w11;
        const float w00 = 1.0f - fxc - w10;
        float4 o;
        o.x = fmaf(a11.x, w11, fmaf(a10.x, w10, fmaf(a01.x, w01, a00.x * w00)));
        o.y = fmaf(a11.y, w11, fmaf(a10.y, w10, fmaf(a01.y, w01, a00.y * w00)));
        o.z = fmaf(a11.z, w11, fmaf(a10.z, w10, fmaf(a01.z, w01, a00.z * w00)));
        o.w = fmaf(a11.w, w11, fmaf(a10.w, w10, fmaf(a01.w, w01, a00.w * w00)));
        *optr = o;
    }
}

extern "C" void kernel_launch(void* const* d_in, const int* in_sizes, int n_in,
                              void* d_out, int out_size)
{
    const float* img  = (const float*)d_in[0];
    const int*   rois = (const int*)d_in[1];
    float*       out  = (float*)d_out;

    const int grid = NROIS * POOL;        // 3584 CTAs, one per (roi, py)
    roi_pool_kernel<<<grid, 256>>>(img, rois, out);
}